// round 6
// baseline (speedup 1.0000x reference)
#include <cuda_runtime.h>
#include <cstdint>
#include <math.h>

#define DI __device__ __forceinline__

constexpr int NN = 16384;
constexpr int STAGES = 5;
constexpr int KTILE = 32;
constexpr int NITER = NN / KTILE;                 // 512
constexpr int STAGE_BYTES = 32768;                // A(16K) + B(16K)
constexpr uint32_t SM_STAGE = 0;
constexpr uint32_t SM_W = SM_STAGE + STAGES * STAGE_BYTES;    // 163840
constexpr uint32_t SM_BS = SM_W + 16384;                       // 180224
constexpr uint32_t GEMM_SMEM = SM_BS + 512;                    // 180736
constexpr uint32_t PREP_SMEM = 66048 + 16384;                  // Es + W0T

// Inter-layer transposed feature panels: X?T[j][i] = X[i][j], j in [0,128), i in [0,N)
// Values stored pre-rounded to tf32 (rna) so the GEMM mainloop skips B-operand cvt.
__device__ float g_X0T[128 * NN];
__device__ float g_X1T[128 * NN];

// ---------------------------------------------------------------- helpers
DI uint32_t smem_u32(const void* p) {
    uint32_t a;
    asm("{ .reg .u64 t; cvta.to.shared.u64 t, %1; cvt.u32.u64 %0, t; }" : "=r"(a) : "l"(p));
    return a;
}
DI uint32_t sw128(uint32_t b) { return b ^ ((b >> 3) & 0x70); }
DI float eluf(float x) { return x > 0.f ? x : expm1f(x); }

DI void cpa16(uint32_t s, const void* g) {
    asm volatile("cp.async.cg.shared.global [%0], [%1], 16;" :: "r"(s), "l"(g));
}
DI void ldsm4(uint32_t* r, uint32_t addr) {
    asm volatile("ldmatrix.sync.aligned.m8n8.x4.shared.b16 {%0,%1,%2,%3}, [%4];"
                 : "=r"(r[0]), "=r"(r[1]), "=r"(r[2]), "=r"(r[3]) : "r"(addr));
}
DI void to_tf32(uint32_t& x) { asm("cvt.rna.tf32.f32 %0, %0;" : "+r"(x)); }
DI float round_tf32(float f) {
    uint32_t u = __float_as_uint(f);
    to_tf32(u);
    return __uint_as_float(u);
}
DI void mma8(float* d, const uint32_t* a, uint32_t b0, uint32_t b1) {
    asm volatile(
        "mma.sync.aligned.m16n8k8.row.col.f32.tf32.tf32.f32 "
        "{%0,%1,%2,%3}, {%4,%5,%6,%7}, {%8,%9}, {%0,%1,%2,%3};"
        : "+f"(d[0]), "+f"(d[1]), "+f"(d[2]), "+f"(d[3])
        : "r"(a[0]), "r"(a[1]), "r"(a[2]), "r"(a[3]), "r"(b0), "r"(b1));
}

// Load one K-tile (kt) of A(adj rows m0..m0+127) and B(XT rows 0..127) into stage slot.
// Rows are 128B (32 fp32), SW128-swizzled in 16B chunks. 512 threads: 2 chunks each side.
DI void load_stage(uint32_t sb, int slot, int kt, const float* adj, const float* BT,
                   int m0, int tid) {
    uint32_t ab = sb + SM_STAGE + (uint32_t)slot * STAGE_BYTES;
    uint32_t bb = ab + 16384;
    const float* ag = adj + (size_t)m0 * NN + (size_t)kt * KTILE;
    const float* bg = BT + (size_t)kt * KTILE;
#pragma unroll
    for (int i = 0; i < 2; i++) {
        int chunk = tid + (i << 9);          // 0..1023
        int r = chunk >> 3;                  // tile row 0..127
        int c4 = chunk & 7;                  // 16B column group
        uint32_t so = sw128((uint32_t)(r * 128 + c4 * 16));
        cpa16(ab + so, ag + (size_t)r * NN + c4 * 4);
        cpa16(bb + so, bg + (size_t)r * NN + c4 * 4);
    }
}

// ---------------------------------------------------------------- prep: X0T = [elu(zs)@W0 ; elu(zu)@W0]^T
__global__ void __launch_bounds__(512) prep_kernel(const float* __restrict__ z,
                                                   const float* __restrict__ W0,
                                                   float* __restrict__ X0T) {
    extern __shared__ char smem[];
    float* Es = (float*)smem;            // [128][129] elu(z) rows
    float* Ws = (float*)(smem + 66048);  // [64][64]  W0^T: Ws[j][c] = W0[c][j]
    int tid = threadIdx.x;
    int m0 = blockIdx.x * 128;

    for (int e = tid; e < 128 * 128; e += 512) {
        int i = e >> 7, c = e & 127;
        Es[i * 129 + c] = eluf(z[(size_t)(m0 + i) * 128 + c]);
    }
    for (int e = tid; e < 64 * 64; e += 512) {
        int j = e >> 6, c = e & 63;
        Ws[j * 64 + c] = W0[c * 64 + j];
    }
    __syncthreads();

    int i = tid & 127;
    int part = tid >> 7;          // 0..3
    int ho = (part & 1) * 64;     // s/u half
    int j0 = (part >> 1) * 32;    // feature half
    float h[64];
#pragma unroll
    for (int c = 0; c < 64; c++) h[c] = Es[i * 129 + ho + c];
    for (int jj = j0; jj < j0 + 32; jj++) {
        const float4* wr = (const float4*)(Ws + jj * 64);
        float acc = 0.f;
#pragma unroll
        for (int q = 0; q < 16; q++) {
            float4 w = wr[q];
            acc += h[4 * q] * w.x + h[4 * q + 1] * w.y + h[4 * q + 2] * w.z + h[4 * q + 3] * w.w;
        }
        X0T[(size_t)(ho + jj) * NN + m0 + i] = round_tf32(acc);
    }
}

// ---------------------------------------------------------------- fused adj-GEMM + epilogue
// 512 threads = 16 warps = 4(M) x 4(N); warp tile 32x32 = 2x4 mma.m16n8k8 fragments.
// PASS 1: OUT = X1T (next transposed panel via W1, tf32-rounded); PASS 2: final via Wl,bl
template <int PASS>
__global__ void __launch_bounds__(512, 1) gemm_kernel(const float* __restrict__ adj,
                                                      const float* __restrict__ BT,
                                                      const float* __restrict__ bias,
                                                      const float* __restrict__ W2,
                                                      const float* __restrict__ bl,
                                                      float* __restrict__ OUT) {
    extern __shared__ char smem[];
    uint32_t sb = smem_u32(smem);
    int tid = threadIdx.x, wid = tid >> 5, lane = tid & 31;
    int m0 = blockIdx.x * 128;

    // preload epilogue weights + bias (region disjoint from stages)
    {
        float* Wsm = (float*)(smem + SM_W);
        if (PASS == 1) {
            for (int e = tid; e < 64 * 64; e += 512) {      // W1^T: Wsm[j*64+c] = W1[c][j]
                int j = e >> 6, c = e & 63;
                Wsm[e] = W2[c * 64 + j];
            }
        } else {
            for (int e = tid; e < 128 * 32; e += 512) {     // Wl^T: Wsm[j*32+o] = Wl[o][j]
                int j = e >> 5, o = e & 31;
                Wsm[e] = W2[o * 128 + j];
            }
        }
        float* bsm = (float*)(smem + SM_BS);
        if (tid < 128) bsm[tid] = bias[tid & 63];
    }

    // per-lane ldmatrix row/column bases (byte offsets within a stage tile)
    int m_off = (wid & 3) * 32;
    int n_off = (wid >> 2) * 32;
    int r8 = lane & 7;
    uint32_t arow[2], brow[2];
#pragma unroll
    for (int mf = 0; mf < 2; mf++)
        arow[mf] = (uint32_t)((m_off + mf * 16 + r8 + ((lane >> 3) & 1) * 8) * 128);
    uint32_t acol = (uint32_t)((lane >> 4) * 16);
#pragma unroll
    for (int p = 0; p < 2; p++)
        brow[p] = (uint32_t)((n_off + p * 16 + r8 + (lane >> 4) * 8) * 128);
    uint32_t bcol = (uint32_t)(((lane >> 3) & 1) * 16);

    float acc[2][4][4];
#pragma unroll
    for (int mf = 0; mf < 2; mf++)
#pragma unroll
        for (int nf = 0; nf < 4; nf++)
#pragma unroll
            for (int r = 0; r < 4; r++) acc[mf][nf][r] = 0.f;

    // ---- prefetch STAGES-1 k-tiles
    for (int p = 0; p < STAGES - 1; p++) {
        load_stage(sb, p, p, adj, BT, m0, tid);
        asm volatile("cp.async.commit_group;" ::: "memory");
    }
    asm volatile("cp.async.wait_group %0;" :: "n"(STAGES - 2) : "memory");
    __syncthreads();   // stage 0 ready everywhere (also covers Wsm/bsm stores)

    // ---- mainloop
    for (int kt = 0; kt < NITER; kt++) {
        int kl = kt + STAGES - 1;
        if (kl < NITER)
            load_stage(sb, kl % STAGES, kl, adj, BT, m0, tid);   // slot (kt-1)%S: consumed+synced
        asm volatile("cp.async.commit_group;" ::: "memory");

        uint32_t ab = sb + SM_STAGE + (uint32_t)(kt % STAGES) * STAGE_BYTES;
        uint32_t bb = ab + 16384;
#pragma unroll
        for (int s = 0; s < 4; s++) {                            // 4 x k=8 steps
            uint32_t A[2][4], B[2][4];
#pragma unroll
            for (int mf = 0; mf < 2; mf++)
                ldsm4(A[mf], ab + sw128(arow[mf] + acol + (uint32_t)s * 32));
#pragma unroll
            for (int p = 0; p < 2; p++)
                ldsm4(B[p], bb + sw128(brow[p] + bcol + (uint32_t)s * 32));
            // A (adj) must be rounded rna->tf32; B panels are pre-rounded at produce time.
#pragma unroll
            for (int mf = 0; mf < 2; mf++)
#pragma unroll
                for (int q = 0; q < 4; q++) to_tf32(A[mf][q]);
#pragma unroll
            for (int mf = 0; mf < 2; mf++) {
                mma8(acc[mf][0], A[mf], B[0][0], B[0][1]);
                mma8(acc[mf][1], A[mf], B[0][2], B[0][3]);
                mma8(acc[mf][2], A[mf], B[1][0], B[1][1]);
                mma8(acc[mf][3], A[mf], B[1][2], B[1][3]);
            }
        }
        asm volatile("cp.async.wait_group %0;" :: "n"(STAGES - 2) : "memory");
        __syncthreads();   // stage kt+1 visible; all warps done with stage kt
    }

    // ---- epilogue phase 1: accum -> elu(+bias) -> Hs smem (pitch 129)
    float* Hs = (float*)smem;            // reuses stage region
    const int HP = 129;
    float* bsm = (float*)(smem + SM_BS);
#pragma unroll
    for (int mf = 0; mf < 2; mf++)
#pragma unroll
        for (int nf = 0; nf < 4; nf++)
#pragma unroll
            for (int r = 0; r < 4; r++) {
                int row = m_off + mf * 16 + (lane >> 2) + ((r >> 1) << 3);
                int col = n_off + nf * 8 + ((lane & 3) << 1) + (r & 1);
                Hs[row * HP + col] = eluf(acc[mf][nf][r] + bsm[col]);
            }
    __syncthreads();

    // ---- epilogue phase 2
    float* Wsm = (float*)(smem + SM_W);
    if (PASS == 1) {
        // X1T[jo][m0+i] = sum_c Hs[i][ho+c] * W1[c][jo]   (tf32-rounded at store)
        int i = tid & 127;
        int part = tid >> 7;         // 0..3
        int ho = (part & 1) * 64;
        int j0 = (part >> 1) * 32;
        float h[64];
#pragma unroll
        for (int c = 0; c < 64; c++) h[c] = Hs[i * HP + ho + c];
        for (int jj = j0; jj < j0 + 32; jj++) {
            const float4* wr = (const float4*)(Wsm + jj * 64);
            float a = 0.f;
#pragma unroll
            for (int q = 0; q < 16; q++) {
                float4 w = wr[q];
                a += h[4 * q] * w.x + h[4 * q + 1] * w.y + h[4 * q + 2] * w.z + h[4 * q + 3] * w.w;
            }
            OUT[(size_t)(ho + jj) * NN + m0 + i] = round_tf32(a);
        }
    } else {
        // out[m0+r][o] = bl[o] + sum_j Hs[r][j] * Wl[o][j]
        int r = tid >> 2;            // 0..127
        int oh = (tid & 3) << 3;     // 0,8,16,24
        float a[8];
#pragma unroll
        for (int o = 0; o < 8; o++) a[o] = __ldg(bl + oh + o);
        for (int j = 0; j < 128; j++) {
            float hv = Hs[r * HP + j];
            const float4* wr = (const float4*)(Wsm + j * 32 + oh);
#pragma unroll
            for (int q = 0; q < 2; q++) {
                float4 w = wr[q];
                a[4 * q + 0] += hv * w.x;
                a[4 * q + 1] += hv * w.y;
                a[4 * q + 2] += hv * w.z;
                a[4 * q + 3] += hv * w.w;
            }
        }
        float4* op = (float4*)(OUT + (size_t)(m0 + r) * 32 + oh);
#pragma unroll
        for (int q = 0; q < 2; q++)
            op[q] = make_float4(a[4 * q], a[4 * q + 1], a[4 * q + 2], a[4 * q + 3]);
    }
}

// ---------------------------------------------------------------- launch
extern "C" void kernel_launch(void* const* d_in, const int* in_sizes, int n_in,
                              void* d_out, int out_size) {
    const float* z   = (const float*)d_in[0];
    const float* adj = (const float*)d_in[1];
    const float* W0  = (const float*)d_in[2];
    const float* b0  = (const float*)d_in[3];
    const float* W1  = (const float*)d_in[4];
    const float* b1  = (const float*)d_in[5];
    const float* Wl  = (const float*)d_in[6];
    const float* bl  = (const float*)d_in[7];
    float* out = (float*)d_out;

    float *x0t = nullptr, *x1t = nullptr;
    cudaGetSymbolAddress((void**)&x0t, g_X0T);
    cudaGetSymbolAddress((void**)&x1t, g_X1T);

    cudaFuncSetAttribute(prep_kernel, cudaFuncAttributeMaxDynamicSharedMemorySize, PREP_SMEM);
    cudaFuncSetAttribute(gemm_kernel<1>, cudaFuncAttributeMaxDynamicSharedMemorySize, GEMM_SMEM);
    cudaFuncSetAttribute(gemm_kernel<2>, cudaFuncAttributeMaxDynamicSharedMemorySize, GEMM_SMEM);

    prep_kernel<<<NN / 128, 512, PREP_SMEM>>>(z, W0, x0t);
    gemm_kernel<1><<<NN / 128, 512, GEMM_SMEM>>>(adj, x0t, b0, W1, nullptr, x1t);
    gemm_kernel<2><<<NN / 128, 512, GEMM_SMEM>>>(adj, x1t, b1, Wl, bl, out);
}

// round 10
// speedup vs baseline: 1.2571x; 1.2571x over previous
#include <cuda_runtime.h>
#include <cuda_fp16.h>
#include <cstdint>
#include <math.h>

#define DI __device__ __forceinline__

constexpr int NN = 16384;
constexpr int STAGES = 4;
constexpr int KTILE = 64;
constexpr int NITER = NN / KTILE;                 // 256
constexpr int STAGE_BYTES = 32768;                // A fp16 16K + B fp16 16K
constexpr uint32_t SM_STAGE = 0;
constexpr uint32_t SM_W = SM_STAGE + STAGES * STAGE_BYTES;    // 131072
constexpr uint32_t SM_BS = SM_W + 16384;                       // 147456
constexpr uint32_t GEMM_SMEM = SM_BS + 512;                    // 147968
constexpr uint32_t PREP_SMEM = 66048 + 16384;                  // Es + W0T

// Inter-layer transposed feature panels (fp16): X?T[j][i] = X[i][j]
__device__ __half g_X0T[128 * NN];
__device__ __half g_X1T[128 * NN];

// ---------------------------------------------------------------- helpers
DI uint32_t smem_u32(const void* p) {
    uint32_t a;
    asm("{ .reg .u64 t; cvta.to.shared.u64 t, %1; cvt.u32.u64 %0, t; }" : "=r"(a) : "l"(p));
    return a;
}
DI uint32_t sw128(uint32_t b) { return b ^ ((b >> 3) & 0x70); }
DI float eluf(float x) { return x > 0.f ? x : expm1f(x); }

DI void cpa16(uint32_t s, const void* g) {
    asm volatile("cp.async.cg.shared.global [%0], [%1], 16;" :: "r"(s), "l"(g));
}
DI void ldsm4(uint32_t* r, uint32_t addr) {
    asm volatile("ldmatrix.sync.aligned.m8n8.x4.shared.b16 {%0,%1,%2,%3}, [%4];"
                 : "=r"(r[0]), "=r"(r[1]), "=r"(r[2]), "=r"(r[3]) : "r"(addr));
}
DI void mma16(float* d, const uint32_t* a, uint32_t b0, uint32_t b1) {
    asm volatile(
        "mma.sync.aligned.m16n8k16.row.col.f32.f16.f16.f32 "
        "{%0,%1,%2,%3}, {%4,%5,%6,%7}, {%8,%9}, {%0,%1,%2,%3};"
        : "+f"(d[0]), "+f"(d[1]), "+f"(d[2]), "+f"(d[3])
        : "r"(a[0]), "r"(a[1]), "r"(a[2]), "r"(a[3]), "r"(b0), "r"(b1));
}
DI uint32_t pack_h2(float lo, float hi) {
    __half2 h = __floats2half2_rn(lo, hi);
    return *reinterpret_cast<uint32_t*>(&h);
}

// ---------------------------------------------------------------- prep: X0T = [elu(zs)@W0 ; elu(zu)@W0]^T  (fp16)
__global__ void __launch_bounds__(512) prep_kernel(const float* __restrict__ z,
                                                   const float* __restrict__ W0,
                                                   __half* __restrict__ X0T) {
    extern __shared__ char smem[];
    float* Es = (float*)smem;            // [128][129] elu(z) rows
    float* Ws = (float*)(smem + 66048);  // [64][64]  W0^T: Ws[j][c] = W0[c][j]
    int tid = threadIdx.x;
    int m0 = blockIdx.x * 128;

    for (int e = tid; e < 128 * 128; e += 512) {
        int i = e >> 7, c = e & 127;
        Es[i * 129 + c] = eluf(z[(size_t)(m0 + i) * 128 + c]);
    }
    for (int e = tid; e < 64 * 64; e += 512) {
        int j = e >> 6, c = e & 63;
        Ws[j * 64 + c] = W0[c * 64 + j];
    }
    __syncthreads();

    int i = tid & 127;
    int part = tid >> 7;          // 0..3
    int ho = (part & 1) * 64;     // s/u half
    int j0 = (part >> 1) * 32;    // feature half
    float h[64];
#pragma unroll
    for (int c = 0; c < 64; c++) h[c] = Es[i * 129 + ho + c];
    for (int jj = j0; jj < j0 + 32; jj++) {
        const float4* wr = (const float4*)(Ws + jj * 64);
        float acc = 0.f;
#pragma unroll
        for (int q = 0; q < 16; q++) {
            float4 w = wr[q];
            acc += h[4 * q] * w.x + h[4 * q + 1] * w.y + h[4 * q + 2] * w.z + h[4 * q + 3] * w.w;
        }
        X0T[(size_t)(ho + jj) * NN + m0 + i] = __float2half_rn(acc);
    }
}

// ---------------------------------------------------------------- fused adj-GEMM + epilogue (fp16 MMA)
// 512 threads = 16 warps = 4(M) x 4(N); warp tile 32x32 = 2x4 m16n8k16 fragments.
// A (adj) converted fp32->fp16 in staging; B panels already fp16.
template <int PASS>
__global__ void __launch_bounds__(512, 1) gemm_kernel(const float* __restrict__ adj,
                                                      const __half* __restrict__ BT,
                                                      const float* __restrict__ bias,
                                                      const float* __restrict__ W2,
                                                      const float* __restrict__ bl,
                                                      float* __restrict__ OUT,
                                                      __half* __restrict__ OUTH) {
    extern __shared__ char smem[];
    uint32_t sb = smem_u32(smem);
    int tid = threadIdx.x, wid = tid >> 5, lane = tid & 31;
    int m0 = blockIdx.x * 128;

    // preload epilogue weights + bias (disjoint from stages)
    {
        float* Wsm = (float*)(smem + SM_W);
        if (PASS == 1) {
            for (int e = tid; e < 64 * 64; e += 512) {      // W1^T
                int j = e >> 6, c = e & 63;
                Wsm[e] = W2[c * 64 + j];
            }
        } else {
            for (int e = tid; e < 128 * 32; e += 512) {     // Wl^T
                int j = e >> 5, o = e & 31;
                Wsm[e] = W2[o * 128 + j];
            }
        }
        float* bsm = (float*)(smem + SM_BS);
        if (tid < 128) bsm[tid] = bias[tid & 63];
    }

    // A-staging (fp32->fp16) indices: 4 threads per row, 16 floats each
    int ar = tid >> 2;                   // adj tile row 0..127
    int aseg = tid & 3;                  // 16-float segment
    const float* agbase = adj + (size_t)(m0 + ar) * NN + aseg * 16;
    uint32_t ast0 = sw128((uint32_t)(ar * 128 + aseg * 32));        // fp16 row pitch 128B
    uint32_t ast1 = sw128((uint32_t)(ar * 128 + aseg * 32 + 16));

    // B-staging: 2 x 16B chunks per thread
    int bc0 = tid, bc1 = tid + 512;      // chunk ids 0..1023: r=chunk>>3, c=chunk&7

    // ldmatrix lane bases (byte offsets in tile; +32*s per k-step, swizzled at use)
    int m_off = (wid & 3) * 32;
    int n_off = (wid >> 2) * 32;
    int r8 = lane & 7;
    uint32_t arow[2], brow[2];
#pragma unroll
    for (int mf = 0; mf < 2; mf++)
        arow[mf] = (uint32_t)((m_off + mf * 16 + r8 + ((lane >> 3) & 1) * 8) * 128);
    uint32_t acolsel = (uint32_t)(((lane >> 4) & 1) * 16);
#pragma unroll
    for (int p = 0; p < 2; p++)
        brow[p] = (uint32_t)((n_off + p * 16 + r8 + ((lane >> 4) & 1) * 8) * 128);
    uint32_t bcolsel = (uint32_t)(((lane >> 3) & 1) * 16);

    float acc[2][4][4];
#pragma unroll
    for (int mf = 0; mf < 2; mf++)
#pragma unroll
        for (int nf = 0; nf < 4; nf++)
#pragma unroll
            for (int r = 0; r < 4; r++) acc[mf][nf][r] = 0.f;

    // ---- prologue: fully stage tiles 0..STAGES-2
    for (int p = 0; p < STAGES - 1; p++) {
        uint32_t ab = sb + (uint32_t)p * STAGE_BYTES;
        uint32_t bb = ab + 16384;
        const float* ag = agbase + (size_t)p * KTILE;
        float4 f0 = ((const float4*)ag)[0], f1 = ((const float4*)ag)[1];
        float4 f2 = ((const float4*)ag)[2], f3 = ((const float4*)ag)[3];
        uint4 u0 = make_uint4(pack_h2(f0.x, f0.y), pack_h2(f0.z, f0.w),
                              pack_h2(f1.x, f1.y), pack_h2(f1.z, f1.w));
        uint4 u1 = make_uint4(pack_h2(f2.x, f2.y), pack_h2(f2.z, f2.w),
                              pack_h2(f3.x, f3.y), pack_h2(f3.z, f3.w));
        *(uint4*)(smem + (ab - sb) + ast0) = u0;
        *(uint4*)(smem + (ab - sb) + ast1) = u1;
        {
            int r = bc0 >> 3, c = bc0 & 7;
            cpa16(bb + sw128((uint32_t)(r * 128 + c * 16)),
                  BT + (size_t)r * NN + (size_t)p * KTILE + c * 8);
            r = bc1 >> 3; c = bc1 & 7;
            cpa16(bb + sw128((uint32_t)(r * 128 + c * 16)),
                  BT + (size_t)r * NN + (size_t)p * KTILE + c * 8);
        }
        asm volatile("cp.async.commit_group;" ::: "memory");
    }
    asm volatile("cp.async.wait_group %0;" :: "n"(STAGES - 2) : "memory");
    __syncthreads();   // stage 0 ready (covers A STS + Wsm/bsm)

    // ---- mainloop
    for (int kt = 0; kt < NITER; kt++) {
        int kl = kt + STAGES - 1;
        uint32_t pslot = (uint32_t)(kl % STAGES) * STAGE_BYTES;
        float4 f0, f1, f2, f3;
        if (kl < NITER) {
            const float* ag = agbase + (size_t)kl * KTILE;
            f0 = ((const float4*)ag)[0]; f1 = ((const float4*)ag)[1];
            f2 = ((const float4*)ag)[2]; f3 = ((const float4*)ag)[3];
            uint32_t bb = sb + pslot + 16384;
            int r = bc0 >> 3, c = bc0 & 7;
            cpa16(bb + sw128((uint32_t)(r * 128 + c * 16)),
                  BT + (size_t)r * NN + (size_t)kl * KTILE + c * 8);
            r = bc1 >> 3; c = bc1 & 7;
            cpa16(bb + sw128((uint32_t)(r * 128 + c * 16)),
                  BT + (size_t)r * NN + (size_t)kl * KTILE + c * 8);
        }
        asm volatile("cp.async.commit_group;" ::: "memory");

        uint32_t ab = sb + (uint32_t)(kt % STAGES) * STAGE_BYTES;
        uint32_t bb = ab + 16384;
#pragma unroll
        for (int s = 0; s < 4; s++) {                            // 4 x k=16 steps
            uint32_t A[2][4], B[2][4];
#pragma unroll
            for (int mf = 0; mf < 2; mf++)
                ldsm4(A[mf], ab + sw128(arow[mf] + acolsel + (uint32_t)s * 32));
#pragma unroll
            for (int p = 0; p < 2; p++)
                ldsm4(B[p], bb + sw128(brow[p] + bcolsel + (uint32_t)s * 32));
#pragma unroll
            for (int mf = 0; mf < 2; mf++) {
                mma16(acc[mf][0], A[mf], B[0][0], B[0][1]);
                mma16(acc[mf][1], A[mf], B[0][2], B[0][3]);
                mma16(acc[mf][2], A[mf], B[1][0], B[1][1]);
                mma16(acc[mf][3], A[mf], B[1][2], B[1][3]);
            }
        }

        if (kl < NITER) {   // convert + stage prefetched A tile
            uint4 u0 = make_uint4(pack_h2(f0.x, f0.y), pack_h2(f0.z, f0.w),
                                  pack_h2(f1.x, f1.y), pack_h2(f1.z, f1.w));
            uint4 u1 = make_uint4(pack_h2(f2.x, f2.y), pack_h2(f2.z, f2.w),
                                  pack_h2(f3.x, f3.y), pack_h2(f3.z, f3.w));
            *(uint4*)(smem + pslot + ast0) = u0;
            *(uint4*)(smem + pslot + ast1) = u1;
        }
        asm volatile("cp.async.wait_group %0;" :: "n"(STAGES - 2) : "memory");
        __syncthreads();
    }

    // ---- epilogue phase 1: accum -> elu(+bias) -> Hs smem (pitch 129)
    float* Hs = (float*)smem;            // reuses stage region
    const int HP = 129;
    float* bsm = (float*)(smem + SM_BS);
#pragma unroll
    for (int mf = 0; mf < 2; mf++)
#pragma unroll
        for (int nf = 0; nf < 4; nf++)
#pragma unroll
            for (int r = 0; r < 4; r++) {
                int row = m_off + mf * 16 + (lane >> 2) + ((r >> 1) << 3);
                int col = n_off + nf * 8 + ((lane & 3) << 1) + (r & 1);
                Hs[row * HP + col] = eluf(acc[mf][nf][r] + bsm[col]);
            }
    __syncthreads();

    // ---- epilogue phase 2
    float* Wsm = (float*)(smem + SM_W);
    if (PASS == 1) {
        // X1T[jo][m0+i] = sum_c Hs[i][ho+c] * W1[c][jo]   (fp16 store)
        int i = tid & 127;
        int part = tid >> 7;
        int ho = (part & 1) * 64;
        int j0 = (part >> 1) * 32;
        float h[64];
#pragma unroll
        for (int c = 0; c < 64; c++) h[c] = Hs[i * HP + ho + c];
        for (int jj = j0; jj < j0 + 32; jj++) {
            const float4* wr = (const float4*)(Wsm + jj * 64);
            float a = 0.f;
#pragma unroll
            for (int q = 0; q < 16; q++) {
                float4 w = wr[q];
                a += h[4 * q] * w.x + h[4 * q + 1] * w.y + h[4 * q + 2] * w.z + h[4 * q + 3] * w.w;
            }
            OUTH[(size_t)(ho + jj) * NN + m0 + i] = __float2half_rn(a);
        }
    } else {
        // out[m0+r][o] = bl[o] + sum_j Hs[r][j] * Wl[o][j]
        int r = tid >> 2;            // 0..127
        int oh = (tid & 3) << 3;     // 0,8,16,24
        float a[8];
#pragma unroll
        for (int o = 0; o < 8; o++) a[o] = __ldg(bl + oh + o);
        for (int j = 0; j < 128; j++) {
            float hv = Hs[r * HP + j];
            const float4* wr = (const float4*)(Wsm + j * 32 + oh);
#pragma unroll
            for (int q = 0; q < 2; q++) {
                float4 w = wr[q];
                a[4 * q + 0] += hv * w.x;
                a[4 * q + 1] += hv * w.y;
                a[4 * q + 2] += hv * w.z;
                a[4 * q + 3] += hv * w.w;
            }
        }
        float4* op = (float4*)(OUT + (size_t)(m0 + r) * 32 + oh);
#pragma unroll
        for (int q = 0; q < 2; q++)
            op[q] = make_float4(a[4 * q], a[4 * q + 1], a[4 * q + 2], a[4 * q + 3]);
    }
}

// ---------------------------------------------------------------- launch
extern "C" void kernel_launch(void* const* d_in, const int* in_sizes, int n_in,
                              void* d_out, int out_size) {
    const float* z   = (const float*)d_in[0];
    const float* adj = (const float*)d_in[1];
    const float* W0  = (const float*)d_in[2];
    const float* b0  = (const float*)d_in[3];
    const float* W1  = (const float*)d_in[4];
    const float* b1  = (const float*)d_in[5];
    const float* Wl  = (const float*)d_in[6];
    const float* bl  = (const float*)d_in[7];
    float* out = (float*)d_out;

    __half *x0t = nullptr, *x1t = nullptr;
    cudaGetSymbolAddress((void**)&x0t, g_X0T);
    cudaGetSymbolAddress((void**)&x1t, g_X1T);

    cudaFuncSetAttribute(prep_kernel, cudaFuncAttributeMaxDynamicSharedMemorySize, PREP_SMEM);
    cudaFuncSetAttribute(gemm_kernel<1>, cudaFuncAttributeMaxDynamicSharedMemorySize, GEMM_SMEM);
    cudaFuncSetAttribute(gemm_kernel<2>, cudaFuncAttributeMaxDynamicSharedMemorySize, GEMM_SMEM);

    prep_kernel<<<NN / 128, 512, PREP_SMEM>>>(z, W0, x0t);
    gemm_kernel<1><<<NN / 128, 512, GEMM_SMEM>>>(adj, x0t, b0, W1, nullptr, nullptr, x1t);
    gemm_kernel<2><<<NN / 128, 512, GEMM_SMEM>>>(adj, x1t, b1, Wl, bl, out, nullptr);
}